// round 12
// baseline (speedup 1.0000x reference)
#include <cuda_runtime.h>
#include <cuda_fp16.h>

// ROI Align via fp16 NHWC relayout (two-kernel, sequential).
//  Pass 1: NCHW fp32 -> NHWC fp16 scratch (62 MB), ldcs streaming reads,
//          64x64 tiles (7600 blocks).
//  Pass 2: block = (ROI, channel-half). 8 warps; warp = output position;
//          lane = 4 channels (uint2). Per-ROI weight/offset tables in smem;
//          half2 8-term FMA chains per sy-row, fp32 accumulation across sy.
//          Constant t00 table (no divisions); division-free coalesced flush.

#define NCH   256
#define FH    200
#define FW    304
#define HW    (FH*FW)        // 60800
#define POUT  7
#define OPP   49
#define S14   14
#define CHB   128            // channels per ROI block
#define SMP   133            // staging pitch (floats), 133 mod 32 = 5

__device__ unsigned int g_nh[(size_t)2 * HW * (NCH/2)];   // fp16x2 NHWC, 62 MB

// t00[p] = 28*(p/7) + 2*(p%7)  (table index of subsample (2*ph, 2*pw))
__constant__ unsigned char c_t00[OPP] = {
      0,  2,  4,  6,  8, 10, 12,
     28, 30, 32, 34, 36, 38, 40,
     56, 58, 60, 62, 64, 66, 68,
     84, 86, 88, 90, 92, 94, 96,
    112,114,116,118,120,122,124,
    140,142,144,146,148,150,152,
    168,170,172,174,176,178,180
};

// ---------------- Pass 1: NCHW fp32 -> NHWC fp16 ----------------
__global__ void __launch_bounds__(256)
to_nhwc_h(const float* __restrict__ in)
{
    __shared__ float tile[64][65];
    const int b   = blockIdx.z;
    const int c0  = blockIdx.y * 64;
    const int hw0 = blockIdx.x * 64;
    const int tx  = threadIdx.x;            // 0..31
    const int ty  = threadIdx.y;            // 0..7

    const float* src = in + (size_t)(b * NCH + c0) * HW + hw0;
#pragma unroll
    for (int k = 0; k < 8; k++) {
        tile[tx][ty + 8*k]      = __ldcs(&src[(size_t)(ty + 8*k) * HW + tx]);
        tile[tx + 32][ty + 8*k] = __ldcs(&src[(size_t)(ty + 8*k) * HW + tx + 32]);
    }
    __syncthreads();

    unsigned int* dst = g_nh + (size_t)(b * HW + hw0) * (NCH/2) + (c0 >> 1);
#pragma unroll
    for (int i = 0; i < 8; i++) {
        int hw = i*8 + ty;
        __half2 h = __floats2half2_rn(tile[hw][2*tx], tile[hw][2*tx + 1]);
        dst[(size_t)hw * (NCH/2) + tx] = *(unsigned int*)&h;
    }
}

// ---------------- Pass 2 ----------------
__device__ __forceinline__ void axis_prep(float t, int size,
                                          int& lo, int& hi, float& frac,
                                          float& valid)
{
    valid = (t > -1.0f && t < (float)size) ? 1.0f : 0.0f;
    float tc  = (t < 0.0f) ? 0.0f : t;
    float low = floorf(tc);
    if (low >= (float)(size - 1)) {
        lo = size - 1; hi = size - 1; frac = 0.0f;
    } else {
        lo = (int)low; hi = lo + 1; frac = tc - low;
    }
}

__device__ __forceinline__ __half2 h2(unsigned int u)
{
    return *reinterpret_cast<const __half2*>(&u);
}

__device__ __forceinline__ unsigned int rep_h2(float f)
{
    __half2 h = __float2half2_rn(f);
    return *reinterpret_cast<unsigned int*>(&h);
}

__global__ void __launch_bounds__(256, 5)
roi_align_h2t(const float* __restrict__ boxes,
              float* __restrict__ out)
{
    __shared__ int   sxl[S14], sxh[S14], syl[S14], syh[S14];  // uint2-granular
    __shared__ float sfx[S14], svx[S14], sfy[S14], svy[S14];
    __shared__ uint4 swt[196];          // 4 replicated-half2 corner weights
    __shared__ int4  soff[196];         // 4 combined corner offsets
    __shared__ float sm[OPP * SMP];     // 26.1 KB staging (permuted layout)

    const int r     = blockIdx.x;
    const int chalf = blockIdx.y;
    const int b     = r >> 9;                // 512 boxes per batch
    const int tid   = threadIdx.x;
    const int lane  = tid & 31;
    const int w     = tid >> 5;

    if (tid < 32) {
        float x1 = boxes[r*4+0] * 0.25f;
        float y1 = boxes[r*4+1] * 0.25f;
        float x2 = boxes[r*4+2] * 0.25f;
        float y2 = boxes[r*4+3] * 0.25f;
        float bw = fmaxf(x2 - x1, 1.0f) * (1.0f/POUT);
        float bh = fmaxf(y2 - y1, 1.0f) * (1.0f/POUT);

        if (tid < S14) {
            float xs = x1 + ((float)tid + 0.5f) * 0.5f * bw;
            int lo, hi; float fr, vd;
            axis_prep(xs, FW, lo, hi, fr, vd);
            sxl[tid] = lo * (NCH/4);          // *64 uint2 per texel
            sxh[tid] = hi * (NCH/4);
            sfx[tid] = fr;  svx[tid] = vd;
        } else if (tid >= 16 && tid < 16 + S14) {
            int i = tid - 16;
            float ys = y1 + ((float)i + 0.5f) * 0.5f * bh;
            int lo, hi; float fr, vd;
            axis_prep(ys, FH, lo, hi, fr, vd);
            syl[i] = lo * FW * (NCH/4);
            syh[i] = hi * FW * (NCH/4);
            sfy[i] = fr;  svy[i] = vd;
        }
    }
    __syncthreads();

    if (tid < 196) {
        int iy = tid / S14;
        int ix = tid - iy * S14;
        float fy = sfy[iy], hy = 1.0f - fy;
        float fx = sfx[ix], hx = 1.0f - fx;
        float vv = svy[iy] * svx[ix];
        swt[tid]  = make_uint4(rep_h2(vv*hy*hx), rep_h2(vv*hy*fx),
                               rep_h2(vv*fy*hx), rep_h2(vv*fy*fx));
        int yl = syl[iy], yh = syh[iy];
        int xl = sxl[ix], xh = sxh[ix];
        soff[tid] = make_int4(yl + xl, yl + xh, yh + xl, yh + xh);
    }
    __syncthreads();

    const uint2* __restrict__ base =
        (const uint2*)g_nh + (size_t)b * HW * (NCH/4) + chalf * 32 + lane;

    for (int p = w; p < OPP; p += 8) {
        int t00 = c_t00[p];
        float f0 = 0.f, f1 = 0.f, f2 = 0.f, f3 = 0.f;
#pragma unroll
        for (int sy = 0; sy < 2; sy++) {
            int   i0 = t00 + sy * S14;          // (iy, ix0)
            int4  oa = soff[i0];
            int4  ob = soff[i0 + 1];
            uint4 wa = swt[i0];
            uint4 wb = swt[i0 + 1];

            uint2 qa0 = __ldg(base + oa.x);
            uint2 qa1 = __ldg(base + oa.y);
            uint2 qa2 = __ldg(base + oa.z);
            uint2 qa3 = __ldg(base + oa.w);
            uint2 qb0 = __ldg(base + ob.x);
            uint2 qb1 = __ldg(base + ob.y);
            uint2 qb2 = __ldg(base + ob.z);
            uint2 qb3 = __ldg(base + ob.w);

            // 8-term half2 chains (per register pair)
            __half2 t0 = __hmul2(h2(wa.x), h2(qa0.x));
            __half2 t1 = __hmul2(h2(wa.x), h2(qa0.y));
            t0 = __hfma2(h2(wa.y), h2(qa1.x), t0);
            t1 = __hfma2(h2(wa.y), h2(qa1.y), t1);
            t0 = __hfma2(h2(wa.z), h2(qa2.x), t0);
            t1 = __hfma2(h2(wa.z), h2(qa2.y), t1);
            t0 = __hfma2(h2(wa.w), h2(qa3.x), t0);
            t1 = __hfma2(h2(wa.w), h2(qa3.y), t1);
            t0 = __hfma2(h2(wb.x), h2(qb0.x), t0);
            t1 = __hfma2(h2(wb.x), h2(qb0.y), t1);
            t0 = __hfma2(h2(wb.y), h2(qb1.x), t0);
            t1 = __hfma2(h2(wb.y), h2(qb1.y), t1);
            t0 = __hfma2(h2(wb.z), h2(qb2.x), t0);
            t1 = __hfma2(h2(wb.z), h2(qb2.y), t1);
            t0 = __hfma2(h2(wb.w), h2(qb3.x), t0);
            t1 = __hfma2(h2(wb.w), h2(qb3.y), t1);

            float2 a0 = __half22float2(t0);
            float2 a1 = __half22float2(t1);
            f0 += a0.x; f1 += a0.y;
            f2 += a1.x; f3 += a1.y;
        }
        // permuted staging: local channel 4*lane+j -> offset j*32 + lane.
        float* d = sm + p * SMP + lane;
        d[0]  = f0 * 0.25f;
        d[32] = f1 * 0.25f;
        d[64] = f2 * 0.25f;
        d[96] = f3 * 0.25f;
    }
    __syncthreads();

    // flush: out[r, chalf*128 .. +128, :] = 6272 contiguous floats.
    // incremental (c,p) tracking: 256 = 5*49 + 11, one correction max.
    float* dst = out + (size_t)r * (NCH * OPP) + (size_t)chalf * (CHB * OPP);
    {
        int t = tid;
        int c = tid / OPP;               // 0..5
        int p = tid - c * OPP;
#pragma unroll 1
        for (int i = 0; i < 25; i++) {
            if (t < CHB * OPP)
                __stcs(&dst[t], sm[p * SMP + ((c & 3) << 5) + (c >> 2)]);
            t += 256;
            p += 11; c += 5;
            if (p >= OPP) { p -= OPP; c++; }
        }
    }
}

extern "C" void kernel_launch(void* const* d_in, const int* in_sizes, int n_in,
                              void* d_out, int out_size)
{
    const float* feat  = (const float*)d_in[0];
    const float* boxes = (const float*)d_in[1];
    float* out = (float*)d_out;

    const int R = out_size / (NCH * OPP);    // 1024

    dim3 tgrid(HW / 64, NCH / 64, 2);        // (950, 4, 2) = 7600 blocks
    dim3 tblk(32, 8);
    to_nhwc_h<<<tgrid, tblk>>>(feat);

    dim3 ggrid(R, 2);                        // (1024, 2)
    roi_align_h2t<<<ggrid, 256>>>(boxes, out);
}

// round 13
// speedup vs baseline: 1.0022x; 1.0022x over previous
#include <cuda_runtime.h>
#include <cuda_fp16.h>

// ROI Align via fp16 NHWC relayout (two-kernel, sequential).
//  Pass 1: NCHW fp32 -> NHWC fp16 scratch (62 MB), ldcs streaming reads,
//          64x64 tiles.
//  Pass 2: block = (ROI, channel-half), 224 threads / 7 warps; each warp
//          handles exactly 7 output positions (perfect balance); lane = 4
//          channels (uint2). Per-ROI weight/offset tables in smem; half2
//          8-term FMA chains per sy-row, fp32 accumulation across sy.
//          6 blocks/SM (42 warps).

#define NCH   256
#define FH    200
#define FW    304
#define HW    (FH*FW)        // 60800
#define POUT  7
#define OPP   49
#define S14   14
#define CHB   128            // channels per ROI block
#define SMP   133            // staging pitch (floats), 133 mod 32 = 5
#define RTHREADS 224

__device__ unsigned int g_nh[(size_t)2 * HW * (NCH/2)];   // fp16x2 NHWC, 62 MB

// t00[p] = 28*(p/7) + 2*(p%7)
__constant__ unsigned char c_t00[OPP] = {
      0,  2,  4,  6,  8, 10, 12,
     28, 30, 32, 34, 36, 38, 40,
     56, 58, 60, 62, 64, 66, 68,
     84, 86, 88, 90, 92, 94, 96,
    112,114,116,118,120,122,124,
    140,142,144,146,148,150,152,
    168,170,172,174,176,178,180
};

// ---------------- Pass 1: NCHW fp32 -> NHWC fp16 ----------------
__global__ void __launch_bounds__(256)
to_nhwc_h(const float* __restrict__ in)
{
    __shared__ float tile[64][65];
    const int b   = blockIdx.z;
    const int c0  = blockIdx.y * 64;
    const int hw0 = blockIdx.x * 64;
    const int tx  = threadIdx.x;            // 0..31
    const int ty  = threadIdx.y;            // 0..7

    const float* src = in + (size_t)(b * NCH + c0) * HW + hw0;
#pragma unroll
    for (int k = 0; k < 8; k++) {
        tile[tx][ty + 8*k]      = __ldcs(&src[(size_t)(ty + 8*k) * HW + tx]);
        tile[tx + 32][ty + 8*k] = __ldcs(&src[(size_t)(ty + 8*k) * HW + tx + 32]);
    }
    __syncthreads();

    unsigned int* dst = g_nh + (size_t)(b * HW + hw0) * (NCH/2) + (c0 >> 1);
#pragma unroll
    for (int i = 0; i < 8; i++) {
        int hw = i*8 + ty;
        __half2 h = __floats2half2_rn(tile[hw][2*tx], tile[hw][2*tx + 1]);
        dst[(size_t)hw * (NCH/2) + tx] = *(unsigned int*)&h;
    }
}

// ---------------- Pass 2 ----------------
__device__ __forceinline__ void axis_prep(float t, int size,
                                          int& lo, int& hi, float& frac,
                                          float& valid)
{
    valid = (t > -1.0f && t < (float)size) ? 1.0f : 0.0f;
    float tc  = (t < 0.0f) ? 0.0f : t;
    float low = floorf(tc);
    if (low >= (float)(size - 1)) {
        lo = size - 1; hi = size - 1; frac = 0.0f;
    } else {
        lo = (int)low; hi = lo + 1; frac = tc - low;
    }
}

__device__ __forceinline__ __half2 h2(unsigned int u)
{
    return *reinterpret_cast<const __half2*>(&u);
}

__device__ __forceinline__ unsigned int rep_h2(float f)
{
    __half2 h = __float2half2_rn(f);
    return *reinterpret_cast<unsigned int*>(&h);
}

__global__ void __launch_bounds__(RTHREADS, 6)
roi_align_h2t(const float* __restrict__ boxes,
              float* __restrict__ out)
{
    __shared__ int   sxl[S14], sxh[S14], syl[S14], syh[S14];  // uint2-granular
    __shared__ float sfx[S14], svx[S14], sfy[S14], svy[S14];
    __shared__ uint4 swt[196];          // 4 replicated-half2 corner weights
    __shared__ int4  soff[196];         // 4 combined corner offsets
    __shared__ float sm[OPP * SMP];     // 26.1 KB staging (permuted layout)

    const int r     = blockIdx.x;
    const int chalf = blockIdx.y;
    const int b     = r >> 9;                // 512 boxes per batch
    const int tid   = threadIdx.x;
    const int lane  = tid & 31;
    const int w     = tid >> 5;              // 0..6

    if (tid < 32) {
        float x1 = boxes[r*4+0] * 0.25f;
        float y1 = boxes[r*4+1] * 0.25f;
        float x2 = boxes[r*4+2] * 0.25f;
        float y2 = boxes[r*4+3] * 0.25f;
        float bw = fmaxf(x2 - x1, 1.0f) * (1.0f/POUT);
        float bh = fmaxf(y2 - y1, 1.0f) * (1.0f/POUT);

        if (tid < S14) {
            float xs = x1 + ((float)tid + 0.5f) * 0.5f * bw;
            int lo, hi; float fr, vd;
            axis_prep(xs, FW, lo, hi, fr, vd);
            sxl[tid] = lo * (NCH/4);          // *64 uint2 per texel
            sxh[tid] = hi * (NCH/4);
            sfx[tid] = fr;  svx[tid] = vd;
        } else if (tid >= 16 && tid < 16 + S14) {
            int i = tid - 16;
            float ys = y1 + ((float)i + 0.5f) * 0.5f * bh;
            int lo, hi; float fr, vd;
            axis_prep(ys, FH, lo, hi, fr, vd);
            syl[i] = lo * FW * (NCH/4);
            syh[i] = hi * FW * (NCH/4);
            sfy[i] = fr;  svy[i] = vd;
        }
    }
    __syncthreads();

    if (tid < 196) {
        int iy = tid / S14;
        int ix = tid - iy * S14;
        float fy = sfy[iy], hy = 1.0f - fy;
        float fx = sfx[ix], hx = 1.0f - fx;
        float vv = svy[iy] * svx[ix];
        swt[tid]  = make_uint4(rep_h2(vv*hy*hx), rep_h2(vv*hy*fx),
                               rep_h2(vv*fy*hx), rep_h2(vv*fy*fx));
        int yl = syl[iy], yh = syh[iy];
        int xl = sxl[ix], xh = sxh[ix];
        soff[tid] = make_int4(yl + xl, yl + xh, yh + xl, yh + xh);
    }
    __syncthreads();

    const uint2* __restrict__ base =
        (const uint2*)g_nh + (size_t)b * HW * (NCH/4) + chalf * 32 + lane;

#pragma unroll
    for (int i = 0; i < 7; i++) {
        int p = w * 7 + i;                   // warp w owns positions 7w..7w+6
        int t00 = c_t00[p];
        float f0 = 0.f, f1 = 0.f, f2 = 0.f, f3 = 0.f;
#pragma unroll
        for (int sy = 0; sy < 2; sy++) {
            int   i0 = t00 + sy * S14;       // (iy, ix0)
            int4  oa = soff[i0];
            int4  ob = soff[i0 + 1];
            uint4 wa = swt[i0];
            uint4 wb = swt[i0 + 1];

            uint2 qa0 = __ldg(base + oa.x);
            uint2 qa1 = __ldg(base + oa.y);
            uint2 qa2 = __ldg(base + oa.z);
            uint2 qa3 = __ldg(base + oa.w);
            uint2 qb0 = __ldg(base + ob.x);
            uint2 qb1 = __ldg(base + ob.y);
            uint2 qb2 = __ldg(base + ob.z);
            uint2 qb3 = __ldg(base + ob.w);

            __half2 t0 = __hmul2(h2(wa.x), h2(qa0.x));
            __half2 t1 = __hmul2(h2(wa.x), h2(qa0.y));
            t0 = __hfma2(h2(wa.y), h2(qa1.x), t0);
            t1 = __hfma2(h2(wa.y), h2(qa1.y), t1);
            t0 = __hfma2(h2(wa.z), h2(qa2.x), t0);
            t1 = __hfma2(h2(wa.z), h2(qa2.y), t1);
            t0 = __hfma2(h2(wa.w), h2(qa3.x), t0);
            t1 = __hfma2(h2(wa.w), h2(qa3.y), t1);
            t0 = __hfma2(h2(wb.x), h2(qb0.x), t0);
            t1 = __hfma2(h2(wb.x), h2(qb0.y), t1);
            t0 = __hfma2(h2(wb.y), h2(qb1.x), t0);
            t1 = __hfma2(h2(wb.y), h2(qb1.y), t1);
            t0 = __hfma2(h2(wb.z), h2(qb2.x), t0);
            t1 = __hfma2(h2(wb.z), h2(qb2.y), t1);
            t0 = __hfma2(h2(wb.w), h2(qb3.x), t0);
            t1 = __hfma2(h2(wb.w), h2(qb3.y), t1);

            float2 a0 = __half22float2(t0);
            float2 a1 = __half22float2(t1);
            f0 += a0.x; f1 += a0.y;
            f2 += a1.x; f3 += a1.y;
        }
        // permuted staging: local channel 4*lane+j -> offset j*32 + lane.
        float* d = sm + p * SMP + lane;
        d[0]  = f0 * 0.25f;
        d[32] = f1 * 0.25f;
        d[64] = f2 * 0.25f;
        d[96] = f3 * 0.25f;
    }
    __syncthreads();

    // flush: out[r, chalf*128 .. +128, :] = 6272 contiguous floats.
    // LDS p-stride 133 ≡ 5 mod 32 -> conflict-free.
    float* dst = out + (size_t)r * (NCH * OPP) + (size_t)chalf * (CHB * OPP);
    for (int t = tid; t < CHB * OPP; t += RTHREADS) {
        int c = t / OPP;                 // local channel 0..127
        int p = t - c * OPP;
        __stcs(&dst[t], sm[p * SMP + ((c & 3) << 5) + (c >> 2)]);
    }
}

extern "C" void kernel_launch(void* const* d_in, const int* in_sizes, int n_in,
                              void* d_out, int out_size)
{
    const float* feat  = (const float*)d_in[0];
    const float* boxes = (const float*)d_in[1];
    float* out = (float*)d_out;

    const int R = out_size / (NCH * OPP);    // 1024

    dim3 tgrid(HW / 64, NCH / 64, 2);        // (950, 4, 2)
    dim3 tblk(32, 8);
    to_nhwc_h<<<tgrid, tblk>>>(feat);

    dim3 ggrid(R, 2);                        // (1024, 2)
    roi_align_h2t<<<ggrid, RTHREADS>>>(boxes, out);
}